// round 14
// baseline (speedup 1.0000x reference)
#include <cuda_runtime.h>
#include <cuda_fp16.h>

#define NN 150000
#define NE 2400000
#define CAP 96     // fixed CSR row capacity; deg ~ Poisson(16), P(deg>=60) ~ e-38

// Scratch (static __device__ — no allocations allowed; zero-initialized at load)
__device__ int     g_cnt[NN];          // per-dst counts (zeroed at load & by k_finish)
__device__ int     g_deg[NN];          // final degrees
__device__ int     g_csr[NN * CAP];    // src grouped by dst, fixed-stride rows (57.6 MB)
__device__ float   g_dinv[NN];
__device__ __half2 g_xs16[NN * 4];     // x*dinv fp16, padded 6->8 (2.4 MB)
__device__ __half2 g_hs16[NN * 16];    // (h@W2)*dinv fp16        (9.6 MB)

// ---------------------------------------------------------------------------
// build: fused histogram + CSR fill. slot = d*CAP + atomicAdd(cnt[d],1).
__global__ void k_build(const int* __restrict__ src, const int* __restrict__ dst, int ne) {
    int e = (blockIdx.x * blockDim.x + threadIdx.x) * 4;
    if (e + 3 < ne) {
        int4 d = __ldg((const int4*)(dst + e));
        int4 s = __ldg((const int4*)(src + e));
        int r0 = atomicAdd(&g_cnt[d.x], 1);
        int r1 = atomicAdd(&g_cnt[d.y], 1);
        int r2 = atomicAdd(&g_cnt[d.z], 1);
        int r3 = atomicAdd(&g_cnt[d.w], 1);
        g_csr[d.x * CAP + r0] = s.x;
        g_csr[d.y * CAP + r1] = s.y;
        g_csr[d.z * CAP + r2] = s.z;
        g_csr[d.w * CAP + r3] = s.w;
    } else {
        for (; e < ne; e++) {
            int d = __ldg(&dst[e]);
            int r = atomicAdd(&g_cnt[d], 1);
            g_csr[d * CAP + r] = __ldg(&src[e]);
        }
    }
}

// finish: deg = cnt; cnt = 0 (ready for next replay); dinv; xs16 = fp16(x*dinv)
__global__ void k_finish(const float* __restrict__ x, int n) {
    int i = blockIdx.x * blockDim.x + threadIdx.x;
    if (i >= n) return;
    int cnt = g_cnt[i];
    g_cnt[i] = 0;
    g_deg[i] = cnt;
    float dinv = rsqrtf((float)cnt + 1.0f);
    g_dinv[i] = dinv;
    const float2* x2 = (const float2*)x;
    float2 a0 = __ldg(&x2[i * 3 + 0]);
    float2 a1 = __ldg(&x2[i * 3 + 1]);
    float2 a2 = __ldg(&x2[i * 3 + 2]);
    __half2 h0 = __float22half2_rn(make_float2(a0.x * dinv, a0.y * dinv));
    __half2 h1 = __float22half2_rn(make_float2(a1.x * dinv, a1.y * dinv));
    __half2 h2 = __float22half2_rn(make_float2(a2.x * dinv, a2.y * dinv));
    __half2 h3 = __float22half2_rn(make_float2(0.f, 0.f));
    uint4 pk;
    pk.x = *(unsigned*)&h0; pk.y = *(unsigned*)&h1;
    pk.z = *(unsigned*)&h2; pk.w = *(unsigned*)&h3;
    ((uint4*)g_xs16)[i] = pk;
}

// ---------------------------------------------------------------------------
// dequant-accumulate one uint4 (8 fp16) into f[0..7]
__device__ __forceinline__ void acc8(float* f, const uint4& u) {
    float2 t0 = __half22float2(*(const __half2*)&u.x);
    float2 t1 = __half22float2(*(const __half2*)&u.y);
    float2 t2 = __half22float2(*(const __half2*)&u.z);
    float2 t3 = __half22float2(*(const __half2*)&u.w);
    f[0] += t0.x; f[1] += t0.y; f[2] += t1.x; f[3] += t1.y;
    f[4] += t2.x; f[5] += t2.y; f[6] += t3.x; f[7] += t3.y;
}

// conv1 fused: gather xs16 over CSR (+self) -> aggx; h=relu(aggx@W1+b1);
// hw=h@W2; write hs16 = fp16(hw*dinv). Thread per node, unroll 4, 16B rows.
__global__ void k_conv1(const float* __restrict__ W1, const float* __restrict__ b1,
                        const float* __restrict__ W2, int n) {
    __shared__ float sW1[6 * 32];
    __shared__ float sb1[32];
    __shared__ float sW2[32 * 32];
    for (int t = threadIdx.x; t < 192; t += blockDim.x) sW1[t] = W1[t];
    for (int t = threadIdx.x; t < 1024; t += blockDim.x) sW2[t] = W2[t];
    if (threadIdx.x < 32) sb1[threadIdx.x] = b1[threadIdx.x];
    __syncthreads();
    int i = blockIdx.x * blockDim.x + threadIdx.x;
    if (i >= n) return;

    float dinv = g_dinv[i];
    const uint4* xs = (const uint4*)g_xs16;
    const int* row = &g_csr[i * CAP];
    int deg = g_deg[i];

    float c[8];
#pragma unroll
    for (int q = 0; q < 8; q++) c[q] = 0.f;
    {   // self term
        uint4 u = __ldg(&xs[i]);
        acc8(c, u);
    }
    int j = 0;
    for (; j + 3 < deg; j += 4) {
        int s0 = __ldg(&row[j + 0]);
        int s1 = __ldg(&row[j + 1]);
        int s2 = __ldg(&row[j + 2]);
        int s3 = __ldg(&row[j + 3]);
        uint4 u0 = __ldg(&xs[s0]);
        uint4 u1 = __ldg(&xs[s1]);
        uint4 u2 = __ldg(&xs[s2]);
        uint4 u3 = __ldg(&xs[s3]);
        acc8(c, u0); acc8(c, u1); acc8(c, u2); acc8(c, u3);
    }
    for (; j < deg; j++) {
        int s0 = __ldg(&row[j]);
        uint4 u0 = __ldg(&xs[s0]);
        acc8(c, u0);
    }
    float a[6] = {c[0] * dinv, c[1] * dinv, c[2] * dinv,
                  c[3] * dinv, c[4] * dinv, c[5] * dinv};

    float h[32];
#pragma unroll
    for (int jj = 0; jj < 32; jj++) {
        float s = sb1[jj];
#pragma unroll
        for (int k = 0; k < 6; k++) s += a[k] * sW1[k * 32 + jj];
        h[jj] = fmaxf(s, 0.f);
    }
    float acc[32];
#pragma unroll
    for (int jj = 0; jj < 32; jj++) acc[jj] = 0.f;
#pragma unroll
    for (int k = 0; k < 32; k++) {
        float hk = h[k];
#pragma unroll
        for (int jj = 0; jj < 32; jj++) acc[jj] += hk * sW2[k * 32 + jj];
    }
    __half2 hbuf[16];
#pragma unroll
    for (int q = 0; q < 16; q++)
        hbuf[q] = __float22half2_rn(make_float2(acc[2*q] * dinv, acc[2*q+1] * dinv));
    uint4* o16 = (uint4*)&g_hs16[(long)i * 16];
    const uint4* hb = (const uint4*)hbuf;
#pragma unroll
    for (int q = 0; q < 4; q++) o16[q] = hb[q];
}

// ---------------------------------------------------------------------------
// feat: FOUR threads per node, each owns 8 features (one 16B LDG.128 per edge;
// the 4 lanes of a node cover the full 64B row contiguously). Unroll 4 edges
// => 4 independent loads in flight, low register pressure => high occupancy.
// Quarters meet in smem; lanes 0-63 then run the fused MLP heads (1 thr/node).
__global__ void k_feat(const float* __restrict__ b2,
                       const float* __restrict__ Wt1, const float* __restrict__ bt1,
                       const float* __restrict__ Wt2, const float* __restrict__ bt2,
                       const float* __restrict__ Wa1, const float* __restrict__ ba1,
                       const float* __restrict__ Wa2, const float* __restrict__ ba2,
                       float* __restrict__ out, int n) {
    __shared__ float s_Wt1[32 * 16];
    __shared__ float s_Wa1[32 * 16];
    __shared__ float s_Wa2[16 * 6];
    __shared__ float s_b2[32];
    __shared__ float s_bt1[16], s_Wt2[16], s_ba1[16], s_ba2[6];
    __shared__ float s_bt2;
    __shared__ float sf[64][33];    // 64 nodes/block

    for (int t = threadIdx.x; t < 512; t += blockDim.x) { s_Wt1[t] = Wt1[t]; s_Wa1[t] = Wa1[t]; }
    for (int t = threadIdx.x; t < 96;  t += blockDim.x) s_Wa2[t] = Wa2[t];
    if (threadIdx.x < 32) s_b2[threadIdx.x] = b2[threadIdx.x];
    if (threadIdx.x < 16) { s_bt1[threadIdx.x] = bt1[threadIdx.x];
                            s_Wt2[threadIdx.x] = Wt2[threadIdx.x];
                            s_ba1[threadIdx.x] = ba1[threadIdx.x]; }
    if (threadIdx.x < 6)  s_ba2[threadIdx.x] = ba2[threadIdx.x];
    if (threadIdx.x == 0) s_bt2 = bt2[0];
    __syncthreads();

    int local = threadIdx.x >> 2;          // node within block (0..63)
    int qp    = threadIdx.x & 3;           // quarter-row (8 features)
    int d = blockIdx.x * 64 + local;

    if (d < n) {
        const uint4* hs = (const uint4*)g_hs16;  // 4 x uint4 per 32-feat row
        const int* row = &g_csr[d * CAP];
        int deg = g_deg[d];

        float f[8];
#pragma unroll
        for (int q = 0; q < 8; q++) f[q] = 0.f;

        {   // self term
            uint4 u = __ldg(&hs[(long)d * 4 + qp]);
            acc8(f, u);
        }

        int j = 0;
        for (; j + 3 < deg; j += 4) {
            int s0 = __ldg(&row[j + 0]);
            int s1 = __ldg(&row[j + 1]);
            int s2 = __ldg(&row[j + 2]);
            int s3 = __ldg(&row[j + 3]);
            uint4 u0 = __ldg(&hs[(long)s0 * 4 + qp]);
            uint4 u1 = __ldg(&hs[(long)s1 * 4 + qp]);
            uint4 u2 = __ldg(&hs[(long)s2 * 4 + qp]);
            uint4 u3 = __ldg(&hs[(long)s3 * 4 + qp]);
            acc8(f, u0); acc8(f, u1); acc8(f, u2); acc8(f, u3);
        }
        for (; j < deg; j++) {
            int s0 = __ldg(&row[j]);
            uint4 u = __ldg(&hs[(long)s0 * 4 + qp]);
            acc8(f, u);
        }

        float dinv = g_dinv[d];
#pragma unroll
        for (int q = 0; q < 8; q++) f[q] = f[q] * dinv + s_b2[8 * qp + q];

        // features at offset 7*n (4 lanes of a node write 64B contiguous x2)
        float4* fo = (float4*)(out + (long)7 * n + (long)d * 32 + 8 * qp);
        fo[0] = make_float4(f[0], f[1], f[2], f[3]);
        fo[1] = make_float4(f[4], f[5], f[6], f[7]);

#pragma unroll
        for (int q = 0; q < 8; q++) sf[local][8 * qp + q] = f[q];
    }
    __syncthreads();

    // head phase: one thread per node (first 64 threads)
    if (threadIdx.x < 64) {
        int dd = blockIdx.x * 64 + threadIdx.x;
        if (dd < n) {
            const float* f = sf[threadIdx.x];

            float t1[16];
#pragma unroll
            for (int jj = 0; jj < 16; jj++) {
                float s = s_bt1[jj];
#pragma unroll
                for (int k = 0; k < 32; k++) s += f[k] * s_Wt1[k * 16 + jj];
                t1[jj] = fmaxf(s, 0.f);
            }
            float topo = s_bt2;
#pragma unroll
            for (int jj = 0; jj < 16; jj++) topo += t1[jj] * s_Wt2[jj];
            out[dd] = topo;

            float a1h[16];
#pragma unroll
            for (int jj = 0; jj < 16; jj++) {
                float s = s_ba1[jj];
#pragma unroll
                for (int k = 0; k < 32; k++) s += f[k] * s_Wa1[k * 16 + jj];
                a1h[jj] = fmaxf(s, 0.f);
            }
            float attr[6];
#pragma unroll
            for (int m = 0; m < 6; m++) {
                float s = s_ba2[m];
#pragma unroll
                for (int jj = 0; jj < 16; jj++) s += a1h[jj] * s_Wa2[jj * 6 + m];
                attr[m] = s;
            }
            long nb = n;
            out[nb     + (long)dd * 3 + 0] = attr[0];
            out[nb     + (long)dd * 3 + 1] = attr[1];
            out[nb     + (long)dd * 3 + 2] = attr[2];
            out[nb * 4 + (long)dd * 3 + 0] = attr[3];
            out[nb * 4 + (long)dd * 3 + 1] = attr[4];
            out[nb * 4 + (long)dd * 3 + 2] = attr[5];
        }
    }
}

// ---------------------------------------------------------------------------
extern "C" void kernel_launch(void* const* d_in, const int* in_sizes, int n_in,
                              void* d_out, int out_size) {
    const float* x   = (const float*)d_in[0];
    const int*   ei  = (const int*)d_in[1];
    const float* W1  = (const float*)d_in[2];
    const float* b1  = (const float*)d_in[3];
    const float* W2  = (const float*)d_in[4];
    const float* b2  = (const float*)d_in[5];
    const float* Wt1 = (const float*)d_in[6];
    const float* bt1 = (const float*)d_in[7];
    const float* Wt2 = (const float*)d_in[8];
    const float* bt2 = (const float*)d_in[9];
    const float* Wa1 = (const float*)d_in[10];
    const float* ba1 = (const float*)d_in[11];
    const float* Wa2 = (const float*)d_in[12];
    const float* ba2 = (const float*)d_in[13];
    float* out = (float*)d_out;

    int n  = in_sizes[0] / 6;
    int ne = in_sizes[1] / 2;
    const int* src = ei;
    const int* dst = ei + ne;

    const int B = 256;
    int gn  = (n + B - 1) / B;
    int ge4 = ((ne + 3) / 4 + B - 1) / B;
    int gf  = (n + 63) / 64;

    k_build <<<ge4, B>>>(src, dst, ne);
    k_finish<<<gn, B>>>(x, n);
    k_conv1 <<<gn, B>>>(W1, b1, W2, n);
    k_feat  <<<gf, B>>>(b2, Wt1, bt1, Wt2, bt2, Wa1, ba1, Wa2, ba2, out, n);
}

// round 15
// speedup vs baseline: 1.0594x; 1.0594x over previous
#include <cuda_runtime.h>
#include <cuda_fp16.h>

#define NN 150000
#define NE 2400000
#define CAP 96     // fixed CSR row capacity; deg ~ Poisson(16), P(deg>=60) ~ e-38

// Scratch (static __device__ — no allocations allowed; zero-initialized at load)
__device__ int     g_cnt[NN];          // per-dst counts (zeroed at load & by k_finish)
__device__ int     g_deg[NN];          // final degrees
__device__ int     g_csr[NN * CAP];    // src grouped by dst, fixed-stride rows (57.6 MB)
__device__ float   g_dinv[NN];
__device__ __half2 g_xs16[NN * 4];     // x*dinv fp16, padded 6->8 (2.4 MB)
__device__ __half2 g_hs16[NN * 16];    // (h@W2)*dinv fp16        (9.6 MB)

// ---------------------------------------------------------------------------
// build: fused histogram + CSR fill. slot = d*CAP + atomicAdd(cnt[d],1).
__global__ void k_build(const int* __restrict__ src, const int* __restrict__ dst, int ne) {
    int e = (blockIdx.x * blockDim.x + threadIdx.x) * 4;
    if (e + 3 < ne) {
        int4 d = __ldg((const int4*)(dst + e));
        int4 s = __ldg((const int4*)(src + e));
        int r0 = atomicAdd(&g_cnt[d.x], 1);
        int r1 = atomicAdd(&g_cnt[d.y], 1);
        int r2 = atomicAdd(&g_cnt[d.z], 1);
        int r3 = atomicAdd(&g_cnt[d.w], 1);
        g_csr[d.x * CAP + r0] = s.x;
        g_csr[d.y * CAP + r1] = s.y;
        g_csr[d.z * CAP + r2] = s.z;
        g_csr[d.w * CAP + r3] = s.w;
    } else {
        for (; e < ne; e++) {
            int d = __ldg(&dst[e]);
            int r = atomicAdd(&g_cnt[d], 1);
            g_csr[d * CAP + r] = __ldg(&src[e]);
        }
    }
}

// finish: deg = cnt; cnt = 0 (ready for next replay); dinv; xs16 = fp16(x*dinv)
__global__ void k_finish(const float* __restrict__ x, int n) {
    int i = blockIdx.x * blockDim.x + threadIdx.x;
    if (i >= n) return;
    int cnt = g_cnt[i];
    g_cnt[i] = 0;
    g_deg[i] = cnt;
    float dinv = rsqrtf((float)cnt + 1.0f);
    g_dinv[i] = dinv;
    const float2* x2 = (const float2*)x;
    float2 a0 = __ldg(&x2[i * 3 + 0]);
    float2 a1 = __ldg(&x2[i * 3 + 1]);
    float2 a2 = __ldg(&x2[i * 3 + 2]);
    __half2 h0 = __float22half2_rn(make_float2(a0.x * dinv, a0.y * dinv));
    __half2 h1 = __float22half2_rn(make_float2(a1.x * dinv, a1.y * dinv));
    __half2 h2 = __float22half2_rn(make_float2(a2.x * dinv, a2.y * dinv));
    __half2 h3 = __float22half2_rn(make_float2(0.f, 0.f));
    uint4 pk;
    pk.x = *(unsigned*)&h0; pk.y = *(unsigned*)&h1;
    pk.z = *(unsigned*)&h2; pk.w = *(unsigned*)&h3;
    ((uint4*)g_xs16)[i] = pk;
}

// ---------------------------------------------------------------------------
// dequant-accumulate one uint4 (8 fp16) into f[0..7]
__device__ __forceinline__ void acc8(float* f, const uint4& u) {
    float2 t0 = __half22float2(*(const __half2*)&u.x);
    float2 t1 = __half22float2(*(const __half2*)&u.y);
    float2 t2 = __half22float2(*(const __half2*)&u.z);
    float2 t3 = __half22float2(*(const __half2*)&u.w);
    f[0] += t0.x; f[1] += t0.y; f[2] += t1.x; f[3] += t1.y;
    f[4] += t2.x; f[5] += t2.y; f[6] += t3.x; f[7] += t3.y;
}

// conv1 fused: gather xs16 over CSR (+self) -> aggx; h=relu(aggx@W1+b1);
// hw=h@W2; write hs16 = fp16(hw*dinv). Thread per node, unroll 4, 16B rows.
__global__ void k_conv1(const float* __restrict__ W1, const float* __restrict__ b1,
                        const float* __restrict__ W2, int n) {
    __shared__ float sW1[6 * 32];
    __shared__ float sb1[32];
    __shared__ float sW2[32 * 32];
    for (int t = threadIdx.x; t < 192; t += blockDim.x) sW1[t] = W1[t];
    for (int t = threadIdx.x; t < 1024; t += blockDim.x) sW2[t] = W2[t];
    if (threadIdx.x < 32) sb1[threadIdx.x] = b1[threadIdx.x];
    __syncthreads();
    int i = blockIdx.x * blockDim.x + threadIdx.x;
    if (i >= n) return;

    float dinv = g_dinv[i];
    const uint4* xs = (const uint4*)g_xs16;
    const int* row = &g_csr[i * CAP];
    int deg = g_deg[i];

    float c[8];
#pragma unroll
    for (int q = 0; q < 8; q++) c[q] = 0.f;
    {   // self term
        uint4 u = __ldg(&xs[i]);
        acc8(c, u);
    }
    int j = 0;
    for (; j + 3 < deg; j += 4) {
        int s0 = __ldg(&row[j + 0]);
        int s1 = __ldg(&row[j + 1]);
        int s2 = __ldg(&row[j + 2]);
        int s3 = __ldg(&row[j + 3]);
        uint4 u0 = __ldg(&xs[s0]);
        uint4 u1 = __ldg(&xs[s1]);
        uint4 u2 = __ldg(&xs[s2]);
        uint4 u3 = __ldg(&xs[s3]);
        acc8(c, u0); acc8(c, u1); acc8(c, u2); acc8(c, u3);
    }
    for (; j < deg; j++) {
        int s0 = __ldg(&row[j]);
        uint4 u0 = __ldg(&xs[s0]);
        acc8(c, u0);
    }
    float a[6] = {c[0] * dinv, c[1] * dinv, c[2] * dinv,
                  c[3] * dinv, c[4] * dinv, c[5] * dinv};

    float h[32];
#pragma unroll
    for (int jj = 0; jj < 32; jj++) {
        float s = sb1[jj];
#pragma unroll
        for (int k = 0; k < 6; k++) s += a[k] * sW1[k * 32 + jj];
        h[jj] = fmaxf(s, 0.f);
    }
    float acc[32];
#pragma unroll
    for (int jj = 0; jj < 32; jj++) acc[jj] = 0.f;
#pragma unroll
    for (int k = 0; k < 32; k++) {
        float hk = h[k];
#pragma unroll
        for (int jj = 0; jj < 32; jj++) acc[jj] += hk * sW2[k * 32 + jj];
    }
    __half2 hbuf[16];
#pragma unroll
    for (int q = 0; q < 16; q++)
        hbuf[q] = __float22half2_rn(make_float2(acc[2*q] * dinv, acc[2*q+1] * dinv));
    uint4* o16 = (uint4*)&g_hs16[(long)i * 16];
    const uint4* hb = (const uint4*)hbuf;
#pragma unroll
    for (int q = 0; q < 4; q++) o16[q] = hb[q];
}

// ---------------------------------------------------------------------------
// feat (gather ONLY — heads split out): FOUR threads per node, each owns 8
// features (one 16B LDG.128 per edge; 4 lanes cover the 64B row contiguously).
// Lean register footprint + launch_bounds => high occupancy.
__global__ void __launch_bounds__(256, 6)
k_feat(const float* __restrict__ b2, float* __restrict__ out, int n) {
    __shared__ float s_b2[32];
    if (threadIdx.x < 32) s_b2[threadIdx.x] = b2[threadIdx.x];
    __syncthreads();

    int local = threadIdx.x >> 2;          // node within block (0..63)
    int qp    = threadIdx.x & 3;           // quarter-row (8 features)
    int d = blockIdx.x * 64 + local;
    if (d >= n) return;

    const uint4* hs = (const uint4*)g_hs16;  // 4 x uint4 per 32-feat row
    const int* row = &g_csr[d * CAP];
    int deg = g_deg[d];

    float f[8];
#pragma unroll
    for (int q = 0; q < 8; q++) f[q] = 0.f;

    {   // self term
        uint4 u = __ldg(&hs[(long)d * 4 + qp]);
        acc8(f, u);
    }

    int j = 0;
    for (; j + 3 < deg; j += 4) {
        int s0 = __ldg(&row[j + 0]);
        int s1 = __ldg(&row[j + 1]);
        int s2 = __ldg(&row[j + 2]);
        int s3 = __ldg(&row[j + 3]);
        uint4 u0 = __ldg(&hs[(long)s0 * 4 + qp]);
        uint4 u1 = __ldg(&hs[(long)s1 * 4 + qp]);
        uint4 u2 = __ldg(&hs[(long)s2 * 4 + qp]);
        uint4 u3 = __ldg(&hs[(long)s3 * 4 + qp]);
        acc8(f, u0); acc8(f, u1); acc8(f, u2); acc8(f, u3);
    }
    for (; j < deg; j++) {
        int s0 = __ldg(&row[j]);
        uint4 u = __ldg(&hs[(long)s0 * 4 + qp]);
        acc8(f, u);
    }

    float dinv = g_dinv[d];
#pragma unroll
    for (int q = 0; q < 8; q++) f[q] = f[q] * dinv + s_b2[8 * qp + q];

    // features at offset 7*n (4 lanes per node write the 128B row contiguously)
    float4* fo = (float4*)(out + (long)7 * n + (long)d * 32 + 8 * qp);
    fo[0] = make_float4(f[0], f[1], f[2], f[3]);
    fo[1] = make_float4(f[4], f[5], f[6], f[7]);
}

// ---------------------------------------------------------------------------
// heads: thread per node; read features back from out (coalesced), run both
// tiny MLPs from smem weights, write topo/normals/uvs.
__global__ void k_heads(const float* __restrict__ Wt1, const float* __restrict__ bt1,
                        const float* __restrict__ Wt2, const float* __restrict__ bt2,
                        const float* __restrict__ Wa1, const float* __restrict__ ba1,
                        const float* __restrict__ Wa2, const float* __restrict__ ba2,
                        float* __restrict__ out, int n) {
    __shared__ float s_Wt1[32 * 16];
    __shared__ float s_Wa1[32 * 16];
    __shared__ float s_Wa2[16 * 6];
    __shared__ float s_bt1[16], s_Wt2[16], s_ba1[16], s_ba2[6];
    __shared__ float s_bt2;
    for (int t = threadIdx.x; t < 512; t += blockDim.x) { s_Wt1[t] = Wt1[t]; s_Wa1[t] = Wa1[t]; }
    for (int t = threadIdx.x; t < 96;  t += blockDim.x) s_Wa2[t] = Wa2[t];
    if (threadIdx.x < 16) { s_bt1[threadIdx.x] = bt1[threadIdx.x];
                            s_Wt2[threadIdx.x] = Wt2[threadIdx.x];
                            s_ba1[threadIdx.x] = ba1[threadIdx.x]; }
    if (threadIdx.x < 6)  s_ba2[threadIdx.x] = ba2[threadIdx.x];
    if (threadIdx.x == 0) s_bt2 = bt2[0];
    __syncthreads();

    int i = blockIdx.x * blockDim.x + threadIdx.x;
    if (i >= n) return;

    float f[32];
    const float4* fi = (const float4*)(out + (long)7 * n + (long)i * 32);
#pragma unroll
    for (int q = 0; q < 8; q++) {
        float4 v = __ldg(&fi[q]);
        f[4*q+0] = v.x; f[4*q+1] = v.y; f[4*q+2] = v.z; f[4*q+3] = v.w;
    }

    float t1[16];
#pragma unroll
    for (int jj = 0; jj < 16; jj++) {
        float s = s_bt1[jj];
#pragma unroll
        for (int k = 0; k < 32; k++) s += f[k] * s_Wt1[k * 16 + jj];
        t1[jj] = fmaxf(s, 0.f);
    }
    float topo = s_bt2;
#pragma unroll
    for (int jj = 0; jj < 16; jj++) topo += t1[jj] * s_Wt2[jj];
    out[i] = topo;

    float a1h[16];
#pragma unroll
    for (int jj = 0; jj < 16; jj++) {
        float s = s_ba1[jj];
#pragma unroll
        for (int k = 0; k < 32; k++) s += f[k] * s_Wa1[k * 16 + jj];
        a1h[jj] = fmaxf(s, 0.f);
    }
    float attr[6];
#pragma unroll
    for (int m = 0; m < 6; m++) {
        float s = s_ba2[m];
#pragma unroll
        for (int jj = 0; jj < 16; jj++) s += a1h[jj] * s_Wa2[jj * 6 + m];
        attr[m] = s;
    }
    long nb = n;
    out[nb     + (long)i * 3 + 0] = attr[0];
    out[nb     + (long)i * 3 + 1] = attr[1];
    out[nb     + (long)i * 3 + 2] = attr[2];
    out[nb * 4 + (long)i * 3 + 0] = attr[3];
    out[nb * 4 + (long)i * 3 + 1] = attr[4];
    out[nb * 4 + (long)i * 3 + 2] = attr[5];
}

// ---------------------------------------------------------------------------
extern "C" void kernel_launch(void* const* d_in, const int* in_sizes, int n_in,
                              void* d_out, int out_size) {
    const float* x   = (const float*)d_in[0];
    const int*   ei  = (const int*)d_in[1];
    const float* W1  = (const float*)d_in[2];
    const float* b1  = (const float*)d_in[3];
    const float* W2  = (const float*)d_in[4];
    const float* b2  = (const float*)d_in[5];
    const float* Wt1 = (const float*)d_in[6];
    const float* bt1 = (const float*)d_in[7];
    const float* Wt2 = (const float*)d_in[8];
    const float* bt2 = (const float*)d_in[9];
    const float* Wa1 = (const float*)d_in[10];
    const float* ba1 = (const float*)d_in[11];
    const float* Wa2 = (const float*)d_in[12];
    const float* ba2 = (const float*)d_in[13];
    float* out = (float*)d_out;

    int n  = in_sizes[0] / 6;
    int ne = in_sizes[1] / 2;
    const int* src = ei;
    const int* dst = ei + ne;

    const int B = 256;
    int gn  = (n + B - 1) / B;
    int ge4 = ((ne + 3) / 4 + B - 1) / B;
    int gf  = (n + 63) / 64;

    k_build <<<ge4, B>>>(src, dst, ne);
    k_finish<<<gn, B>>>(x, n);
    k_conv1 <<<gn, B>>>(W1, b1, W2, n);
    k_feat  <<<gf, B>>>(b2, out, n);
    k_heads <<<gn, B>>>(Wt1, bt1, Wt2, bt2, Wa1, ba1, Wa2, ba2, out, n);
}